// round 5
// baseline (speedup 1.0000x reference)
#include <cuda_runtime.h>

// VectorP1FunctionSpace: P1 FEM interpolation on a structured 32x32
// triangulation of [0,1]^2 (nvert = 33*33 = 1089, maxc = 6 cells/vertex).
//
// Reference computes basis[v] = min_k relu(x . W[v,k] + c[v,k]) for ALL
// vertices, then out = [basis.wx, basis.wy]. Mathematically basis[v] is the
// P1 hat function: it is exactly 0 (relu clamps to 0.0f, min picks it) for
// every vertex NOT belonging to the triangle containing x. So we locate the
// containing triangle analytically and evaluate the reference's exact
// min-over-6 formula using the supplied W/c rows for just those 3 vertices.

static __device__ __forceinline__ float hat_eval(const float* __restrict__ W,
                                                 const float* __restrict__ C,
                                                 int v, float px, float py) {
    const float* Wv = W + (size_t)v * 12;  // [6,2]
    const float* Cv = C + (size_t)v * 6;   // [6], padded slots hold 1e9
    float m = 3.0e30f;
#pragma unroll
    for (int k = 0; k < 6; k++) {
        float w0 = __ldg(Wv + 2 * k + 0);
        float w1 = __ldg(Wv + 2 * k + 1);
        float cc = __ldg(Cv + k);
        float val = fmaf(px, w0, fmaf(py, w1, cc));
        val = fmaxf(val, 0.0f);   // relu
        m = fminf(m, val);        // min over incident cells
    }
    return m;
}

__global__ void __launch_bounds__(256)
VectorP1FunctionSpace_5342939316636_kernel(const float2* __restrict__ x,
                                           const float* __restrict__ W,
                                           const float* __restrict__ C,
                                           const float* __restrict__ wx,
                                           const float* __restrict__ wy,
                                           float2* __restrict__ out,
                                           int n) {
    int idx = blockIdx.x * blockDim.x + threadIdx.x;
    if (idx >= n) return;

    float2 p = x[idx];
    float fx = p.x * 32.0f;
    float fy = p.y * 32.0f;
    int i = (int)fx;  i = i < 0 ? 0 : (i > 31 ? 31 : i);
    int j = (int)fy;  j = j < 0 ? 0 : (j > 31 ? 31 : j);
    float u = fx - (float)i;
    float v = fy - (float)j;

    // vertex ids: v(i,j) = i*33 + j
    int v00 = i * 33 + j;
    int v11 = v00 + 34;                        // (i+1, j+1) — in both triangles
    int v3  = (u >= v) ? (v00 + 33) : (v00 + 1);  // lower tri: v10, upper: v01

    float b0 = hat_eval(W, C, v00, p.x, p.y);
    float b1 = hat_eval(W, C, v11, p.x, p.y);
    float b2 = hat_eval(W, C, v3,  p.x, p.y);

    float ox = fmaf(b0, __ldg(wx + v00),
               fmaf(b1, __ldg(wx + v11),
                    b2 * __ldg(wx + v3)));
    float oy = fmaf(b0, __ldg(wy + v00),
               fmaf(b1, __ldg(wy + v11),
                    b2 * __ldg(wy + v3)));

    out[idx] = make_float2(ox, oy);
}

extern "C" void kernel_launch(void* const* d_in, const int* in_sizes, int n_in,
                              void* d_out, int out_size) {
    const float2* x  = (const float2*)d_in[0];  // [B,N,2] fp32
    const float*  W  = (const float*)d_in[1];   // [1089,6,2]
    const float*  C  = (const float*)d_in[2];   // [1089,6]
    const float*  wx = (const float*)d_in[3];   // [1089]
    const float*  wy = (const float*)d_in[4];   // [1089]
    float2* out = (float2*)d_out;               // [B,N,2] fp32

    int n = in_sizes[0] / 2;  // number of points (B*N)
    int threads = 256;
    int blocks = (n + threads - 1) / threads;
    VectorP1FunctionSpace_5342939316636_kernel<<<blocks, threads>>>(
        x, W, C, wx, wy, out, n);
}

// round 6
// speedup vs baseline: 1.2593x; 1.2593x over previous
#include <cuda_runtime.h>

// VectorP1FunctionSpace: P1 FEM interpolation on a structured 32x32
// triangulation of [0,1]^2 (nvert = 33*33 = 1089).
//
// The reference's basis[v] = min_k relu(x.W[v,k] + c[v,k]) is the P1 hat
// function of vertex v. For a point inside a cell, the hats of the 3 cell
// vertices equal the barycentric coordinates of the point in that cell
// (all other incident-cell planes evaluate >= the containing-cell plane on
// this uniform right-triangle mesh), and every other vertex's hat is exactly
// 0 (relu floor). So the full [B,N,1089] einsum collapses to: locate the
// cell analytically, compute 3 barycentric weights, gather 3 entries each
// of wx/wy. Verified mechanism in R4 via exact min-of-6 replication
// (rel_err 5e-8); analytic weights differ only by fp rounding (~2e-6 abs).

__global__ void __launch_bounds__(128)
VectorP1FunctionSpace_5342939316636_kernel(const float2* __restrict__ x,
                                           const float* __restrict__ wx,
                                           const float* __restrict__ wy,
                                           float2* __restrict__ out,
                                           int n) {
    int idx = blockIdx.x * blockDim.x + threadIdx.x;
    if (idx >= n) return;

    float2 p = x[idx];
    float fx = p.x * 32.0f;
    float fy = p.y * 32.0f;
    int i = (int)fx;  i = i < 0 ? 0 : (i > 31 ? 31 : i);
    int j = (int)fy;  j = j < 0 ? 0 : (j > 31 ? 31 : j);
    float u = fx - (float)i;
    float v = fy - (float)j;

    // vertex ids: v(i,j) = i*33 + j
    int v00 = i * 33 + j;
    int v11 = v00 + 34;  // (i+1, j+1) — shared by both triangles

    bool lower = (u >= v);
    int v3 = lower ? (v00 + 33) : (v00 + 1);  // v10 (lower) or v01 (upper)

    // barycentric weights of the containing triangle
    float b00 = lower ? (1.0f - u) : (1.0f - v);
    float b11 = lower ? v : u;
    float b3  = lower ? (u - v) : (v - u);

    float ox = fmaf(b00, __ldg(wx + v00),
               fmaf(b11, __ldg(wx + v11),
                    b3 * __ldg(wx + v3)));
    float oy = fmaf(b00, __ldg(wy + v00),
               fmaf(b11, __ldg(wy + v11),
                    b3 * __ldg(wy + v3)));

    out[idx] = make_float2(ox, oy);
}

extern "C" void kernel_launch(void* const* d_in, const int* in_sizes, int n_in,
                              void* d_out, int out_size) {
    const float2* x  = (const float2*)d_in[0];  // [B,N,2] fp32
    // d_in[1] = W [1089,6,2], d_in[2] = C [1089,6] — not needed analytically
    const float*  wx = (const float*)d_in[3];   // [1089]
    const float*  wy = (const float*)d_in[4];   // [1089]
    float2* out = (float2*)d_out;               // [B,N,2] fp32

    int n = in_sizes[0] / 2;  // number of points (B*N) = 16384
    int threads = 128;        // spread the small grid across more SMs
    int blocks = (n + threads - 1) / threads;   // 128 blocks
    VectorP1FunctionSpace_5342939316636_kernel<<<blocks, threads>>>(
        x, wx, wy, out, n);
}

// round 7
// speedup vs baseline: 1.2651x; 1.0047x over previous
#include <cuda_runtime.h>

// VectorP1FunctionSpace: P1 FEM interpolation on a structured 32x32
// triangulation of [0,1]^2 (nvert = 33*33 = 1089).
//
// basis[v] = min_k relu(x.W[v,k]+c[v,k]) is the P1 hat of vertex v: exactly 0
// for vertices outside the containing triangle (relu floor), and equal to the
// barycentric coordinate for the 3 triangle vertices (hat is concave on its
// support on this uniform right-triangle mesh). So: locate cell analytically,
// 3 barycentric weights, gather 3 entries each of wx/wy. Mechanism verified
// exactly in R4 (min-of-6 replication, rel_err 5e-8); analytic form matched
// it in R5.
//
// R6: 2 points per thread (float4 in/out) to halve memory instructions and
// double per-warp MLP on the gather fan. Kernel is launch-overhead-bound
// (T_ovh ~5000 cyc); this trims the remaining ~1.3us of T_CTA.

static __device__ __forceinline__ void eval_point(float px, float py,
                                                  const float* __restrict__ wx,
                                                  const float* __restrict__ wy,
                                                  float& ox, float& oy) {
    float fx = px * 32.0f;
    float fy = py * 32.0f;
    int i = (int)fx;  i = i < 0 ? 0 : (i > 31 ? 31 : i);
    int j = (int)fy;  j = j < 0 ? 0 : (j > 31 ? 31 : j);
    float u = fx - (float)i;
    float v = fy - (float)j;

    int v00 = i * 33 + j;        // vertex (i,j)
    int v11 = v00 + 34;          // (i+1,j+1) — shared by both triangles

    bool lower = (u >= v);
    int v3 = lower ? (v00 + 33) : (v00 + 1);   // v10 (lower) / v01 (upper)

    float b00 = lower ? (1.0f - u) : (1.0f - v);
    float b11 = lower ? v : u;
    float b3  = lower ? (u - v) : (v - u);

    ox = fmaf(b00, __ldg(wx + v00),
         fmaf(b11, __ldg(wx + v11),
              b3 * __ldg(wx + v3)));
    oy = fmaf(b00, __ldg(wy + v00),
         fmaf(b11, __ldg(wy + v11),
              b3 * __ldg(wy + v3)));
}

__global__ void __launch_bounds__(64)
VectorP1FunctionSpace_5342939316636_kernel(const float4* __restrict__ x2,
                                           const float* __restrict__ wx,
                                           const float* __restrict__ wy,
                                           float4* __restrict__ out2,
                                           int npair) {
    int idx = blockIdx.x * blockDim.x + threadIdx.x;
    if (idx >= npair) return;

    float4 p = x2[idx];   // two points: (p.x,p.y) and (p.z,p.w)

    float ox0, oy0, ox1, oy1;
    eval_point(p.x, p.y, wx, wy, ox0, oy0);
    eval_point(p.z, p.w, wx, wy, ox1, oy1);

    out2[idx] = make_float4(ox0, oy0, ox1, oy1);
}

extern "C" void kernel_launch(void* const* d_in, const int* in_sizes, int n_in,
                              void* d_out, int out_size) {
    const float4* x2  = (const float4*)d_in[0];  // [B,N,2] fp32, 2 pts/float4
    // d_in[1] = W [1089,6,2], d_in[2] = C [1089,6] — unused (analytic)
    const float*  wx  = (const float*)d_in[3];   // [1089]
    const float*  wy  = (const float*)d_in[4];   // [1089]
    float4* out2 = (float4*)d_out;               // [B,N,2] fp32

    int npair = in_sizes[0] / 4;  // 16384 points -> 8192 pairs
    int threads = 64;
    int blocks = (npair + threads - 1) / threads;  // 128 blocks
    VectorP1FunctionSpace_5342939316636_kernel<<<blocks, threads>>>(
        x2, wx, wy, out2, npair);
}